// round 11
// baseline (speedup 1.0000x reference)
#include <cuda_runtime.h>
#include <cuda_fp16.h>
#include <cstdint>

// NearestEmbed (VQ) via 2-split fp16 mma.sync m16n8k16 (lo scaled by 2^11).
// R11: 16 codes per inner iteration (6 independent MMA chains, shared A frags)
// to hide HMMA latency + amortize finalize; race-free double buffering kept.
// x [32,64,64,64] f32, emb [64,1024] f32
// out = [ result (8388608 f32) | argmin (131072 as f32, if room) ]

typedef uint32_t u32;

#define B_    32
#define D_    64
#define K_    1024
#define HW_   4096
#define NPTS  (B_*HW_)
#define RES_ELEMS (B_*D_*HW_)

#define NT     256
#define PT     128                  // points per block
#define KTILE  128                  // codes per smem tile
#define NTILES (K_/KTILE)           // 8
#define CSTRIDE 320                 // bytes/code in smem (256 data + 64 pad)
#define TILE_SM (KTILE*CSTRIDE)     // 40960
#define SRC_CODE 256                // bytes/code in global scratch

#define OFF_SSQ  (2*TILE_SM)        // 81920: 1024 floats
#define OFF_SIDX (OFF_SSQ + 4096)   // 86016: 128 ints
#define SMEM_TOTAL (OFF_SIDX + 512) // 86528

#define LO_SCALE   2048.0f
#define NEG2LO     (-2.0f/2048.0f)

// scratch cell [code][s][tg]: {h2(h[d0],h[d0+1]), h2(h[d0+8],h[d0+9]),
//                              h2(l'[d0],l'[d0+1]), h2(l'[d0+8],l'[d0+9])}, d0=16s+2tg
__device__ float4 g_split[K_ * 16];  // 256 KB
__device__ float  g_ssq[K_];

__device__ __forceinline__ u32 smem_u32(const void* p) {
    u32 a;
    asm("{ .reg .u64 t; cvta.to.shared.u64 t, %1; cvt.u32.u64 %0, t; }" : "=r"(a) : "l"(p));
    return a;
}
__device__ __forceinline__ void split_h(float v, __half& h, __half& l) {
    h = __float2half_rn(v);
    l = __float2half_rn((v - __half2float(h)) * LO_SCALE);
}
__device__ __forceinline__ u32 pack_h2(__half a, __half b) {
    __half2 p = __halves2half2(a, b);
    return *(u32*)&p;
}
__device__ __forceinline__ void mma16816(float& c0, float& c1, float& c2, float& c3,
                                         u32 a0, u32 a1, u32 a2, u32 a3, u32 b0, u32 b1) {
    asm("mma.sync.aligned.m16n8k16.row.col.f32.f16.f16.f32 "
        "{%0,%1,%2,%3}, {%4,%5,%6,%7}, {%8,%9}, {%0,%1,%2,%3};"
        : "+f"(c0), "+f"(c1), "+f"(c2), "+f"(c3)
        : "r"(a0), "r"(a1), "r"(a2), "r"(a3), "r"(b0), "r"(b1));
}
__device__ __forceinline__ void cp16(u32 dst, const void* src) {
    asm volatile("cp.async.cg.shared.global [%0], [%1], 16;" :: "r"(dst), "l"(src) : "memory");
}
__device__ __forceinline__ void cp_commit() {
    asm volatile("cp.async.commit_group;" ::: "memory");
}
template <int N> __device__ __forceinline__ void cp_wait() {
    asm volatile("cp.async.wait_group %0;" :: "n"(N) : "memory");
}

// ---- prep: split emb into fp16 hi / scaled-lo cells ----
__global__ void prep_split(const float* __restrict__ emb) {
    int c = blockIdx.x * 256 + threadIdx.x;      // 0..16383 cells
    int n = c >> 4, r = c & 15;
    int s = r >> 2, tg = r & 3;
    int d0 = 16 * s + 2 * tg;
    float v0 = emb[(d0    ) * K_ + n];
    float v1 = emb[(d0 + 1) * K_ + n];
    float v8 = emb[(d0 + 8) * K_ + n];
    float v9 = emb[(d0 + 9) * K_ + n];
    __half h0, l0, h1, l1, h8, l8, h9, l9;
    split_h(v0, h0, l0); split_h(v1, h1, l1);
    split_h(v8, h8, l8); split_h(v9, h9, l9);
    float4 cell;
    cell.x = __uint_as_float(pack_h2(h0, h1));
    cell.y = __uint_as_float(pack_h2(h8, h9));
    cell.z = __uint_as_float(pack_h2(l0, l1));
    cell.w = __uint_as_float(pack_h2(l8, l9));
    g_split[c] = cell;
}
__global__ void prep_ssq(const float* __restrict__ emb) {
    int n = blockIdx.x * 256 + threadIdx.x;
    float s = 0.f;
#pragma unroll
    for (int d = 0; d < D_; ++d) { float v = emb[d * K_ + n]; s = fmaf(v, v, s); }
    g_ssq[n] = s;
}

__global__ __launch_bounds__(NT, 2)
void vq_mma_kernel(const float* __restrict__ x, const float* __restrict__ emb,
                   float* __restrict__ out, int out_size)
{
    extern __shared__ __align__(16) char smem[];
    const u32 sbase = smem_u32(smem);
    const int t = threadIdx.x;
    const int w = t >> 5, lane = t & 31;
    const int g = lane >> 2, tg = lane & 3;

    const int n0 = blockIdx.x * PT;
    const int bb = n0 >> 12, rem0 = n0 & 4095;
    const float* xblk = x + bb * (D_ * HW_) + rem0;

    // prologue: prefetch tile 0
    {
        const char* src = (const char*)g_split;
#pragma unroll
        for (int i = 0; i < 8; ++i) {
            int cell = t + 256 * i;
            int nl = cell >> 4, r = cell & 15;
            cp16(sbase + nl * CSTRIDE + r * 16, src + cell * 16);
        }
        cp_commit();
    }

    float* ssq_s = (float*)(smem + OFF_SSQ);
#pragma unroll
    for (int i = 0; i < 4; ++i) ssq_s[t + 256 * i] = g_ssq[t + 256 * i];

    // A fragments: 16 pts (rows w*16+g, +8), dims 16s+2tg+{0,1,8,9}, hi + scaled-lo.
    u32 ah[4][4], al[4][4];
    {
        const float* xw = xblk + w * 16;
#pragma unroll
        for (int s = 0; s < 4; ++s) {
            int d0 = 16 * s + 2 * tg;
            float v;
            __half h0a, l0a, h1a, l1a, h8a, l8a, h9a, l9a;
            __half h0b, l0b, h1b, l1b, h8b, l8b, h9b, l9b;
            v = xw[(d0    ) * HW_ + g];     split_h(v, h0a, l0a);
            v = xw[(d0 + 1) * HW_ + g];     split_h(v, h1a, l1a);
            v = xw[(d0 + 8) * HW_ + g];     split_h(v, h8a, l8a);
            v = xw[(d0 + 9) * HW_ + g];     split_h(v, h9a, l9a);
            v = xw[(d0    ) * HW_ + g + 8]; split_h(v, h0b, l0b);
            v = xw[(d0 + 1) * HW_ + g + 8]; split_h(v, h1b, l1b);
            v = xw[(d0 + 8) * HW_ + g + 8]; split_h(v, h8b, l8b);
            v = xw[(d0 + 9) * HW_ + g + 8]; split_h(v, h9b, l9b);
            ah[s][0] = pack_h2(h0a, h1a);  ah[s][1] = pack_h2(h0b, h1b);
            ah[s][2] = pack_h2(h8a, h9a);  ah[s][3] = pack_h2(h8b, h9b);
            al[s][0] = pack_h2(l0a, l1a);  al[s][1] = pack_h2(l0b, l1b);
            al[s][2] = pack_h2(l8a, l9a);  al[s][3] = pack_h2(l8b, l9b);
        }
    }

    float best0 = 3.402823e38f, best1 = 3.402823e38f;
    int   bidx0 = 0, bidx1 = 0;

    for (int tile = 0; tile < NTILES; ++tile) {
        cp_wait<0>();      // this tile's data landed
        __syncthreads();   // all warps done reading the other buffer

        if (tile + 1 < NTILES) {   // prefetch into the other buffer (readers done)
            const u32  nbuf = sbase + ((tile + 1) & 1) * TILE_SM;
            const char* src = (const char*)g_split + (tile + 1) * (KTILE * SRC_CODE);
#pragma unroll
            for (int i = 0; i < 8; ++i) {
                int cell = t + 256 * i;
                int nl = cell >> 4, r = cell & 15;
                cp16(nbuf + nl * CSTRIDE + r * 16, src + cell * 16);
            }
            cp_commit();
        }

        const char* bufc = smem + (tile & 1) * TILE_SM;
#pragma unroll 1
        for (int pair = 0; pair < 8; ++pair) {   // 16 codes per iteration
            const float4* bpA = (const float4*)(bufc + (pair * 16 + g)     * CSTRIDE + tg * 16);
            const float4* bpB = (const float4*)(bufc + (pair * 16 + 8 + g) * CSTRIDE + tg * 16);
            // 6 chains x 4 accum regs
            float Ahh0=0.f,Ahh1=0.f,Ahh2=0.f,Ahh3=0.f, Acx0=0.f,Acx1=0.f,Acx2=0.f,Acx3=0.f,
                  Alh0=0.f,Alh1=0.f,Alh2=0.f,Alh3=0.f;
            float Bhh0=0.f,Bhh1=0.f,Bhh2=0.f,Bhh3=0.f, Bcx0=0.f,Bcx1=0.f,Bcx2=0.f,Bcx3=0.f,
                  Blh0=0.f,Blh1=0.f,Blh2=0.f,Blh3=0.f;
#pragma unroll
            for (int s = 0; s < 4; ++s) {
                float4 bvA = bpA[s * 4];
                float4 bvB = bpB[s * 4];
                u32 Ah0 = __float_as_uint(bvA.x), Ah1 = __float_as_uint(bvA.y);
                u32 Al0 = __float_as_uint(bvA.z), Al1 = __float_as_uint(bvA.w);
                u32 Bh0 = __float_as_uint(bvB.x), Bh1 = __float_as_uint(bvB.y);
                u32 Bl0 = __float_as_uint(bvB.z), Bl1 = __float_as_uint(bvB.w);
                // interleave the 6 independent chains
                mma16816(Ahh0,Ahh1,Ahh2,Ahh3, ah[s][0],ah[s][1],ah[s][2],ah[s][3], Ah0,Ah1);
                mma16816(Bhh0,Bhh1,Bhh2,Bhh3, ah[s][0],ah[s][1],ah[s][2],ah[s][3], Bh0,Bh1);
                mma16816(Acx0,Acx1,Acx2,Acx3, ah[s][0],ah[s][1],ah[s][2],ah[s][3], Al0,Al1);
                mma16816(Bcx0,Bcx1,Bcx2,Bcx3, ah[s][0],ah[s][1],ah[s][2],ah[s][3], Bl0,Bl1);
                mma16816(Alh0,Alh1,Alh2,Alh3, al[s][0],al[s][1],al[s][2],al[s][3], Ah0,Ah1);
                mma16816(Blh0,Blh1,Blh2,Blh3, al[s][0],al[s][1],al[s][2],al[s][3], Bh0,Bh1);
            }
            // finalize group A (codes kgA, kgA+1) and B (kgB, kgB+1)
            const int kgA = tile * KTILE + pair * 16 + 2 * tg;
            const int kgB = kgA + 8;
            const float sqA0 = ssq_s[kgA], sqA1 = ssq_s[kgA + 1];
            const float sqB0 = ssq_s[kgB], sqB1 = ssq_s[kgB + 1];
            // dist = sq - 2*hh - 2^-11*2*(hl+lh)
            float dA0 = fmaf(NEG2LO, Acx0 + Alh0, fmaf(-2.f, Ahh0, sqA0));
            float dA1 = fmaf(NEG2LO, Acx1 + Alh1, fmaf(-2.f, Ahh1, sqA1));
            float dA2 = fmaf(NEG2LO, Acx2 + Alh2, fmaf(-2.f, Ahh2, sqA0));
            float dA3 = fmaf(NEG2LO, Acx3 + Alh3, fmaf(-2.f, Ahh3, sqA1));
            float dB0 = fmaf(NEG2LO, Bcx0 + Blh0, fmaf(-2.f, Bhh0, sqB0));
            float dB1 = fmaf(NEG2LO, Bcx1 + Blh1, fmaf(-2.f, Bhh1, sqB1));
            float dB2 = fmaf(NEG2LO, Bcx2 + Blh2, fmaf(-2.f, Bhh2, sqB0));
            float dB3 = fmaf(NEG2LO, Bcx3 + Blh3, fmaf(-2.f, Bhh3, sqB1));
            // ascending code order within the scan: strict '<' keeps first index
            if (dA0 < best0) { best0 = dA0; bidx0 = kgA; }
            if (dA1 < best0) { best0 = dA1; bidx0 = kgA + 1; }
            if (dB0 < best0) { best0 = dB0; bidx0 = kgB; }
            if (dB1 < best0) { best0 = dB1; bidx0 = kgB + 1; }
            if (dA2 < best1) { best1 = dA2; bidx1 = kgA; }
            if (dA3 < best1) { best1 = dA3; bidx1 = kgA + 1; }
            if (dB2 < best1) { best1 = dB2; bidx1 = kgB; }
            if (dB3 < best1) { best1 = dB3; bidx1 = kgB + 1; }
        }
    }

    // reduce across the 4 tg-lanes sharing each point row; ties -> smaller index
#pragma unroll
    for (int mask = 1; mask < 4; mask <<= 1) {
        float e0 = __shfl_xor_sync(0xffffffffu, best0, mask, 4);
        int   j0 = __shfl_xor_sync(0xffffffffu, bidx0, mask, 4);
        if (e0 < best0 || (e0 == best0 && j0 < bidx0)) { best0 = e0; bidx0 = j0; }
        float e1 = __shfl_xor_sync(0xffffffffu, best1, mask, 4);
        int   j1 = __shfl_xor_sync(0xffffffffu, bidx1, mask, 4);
        if (e1 < best1 || (e1 == best1 && j1 < bidx1)) { best1 = e1; bidx1 = j1; }
    }
    int* sidx = (int*)(smem + OFF_SIDX);
    if (tg == 0) {
        sidx[w * 16 + g]     = bidx0;
        sidx[w * 16 + 8 + g] = bidx1;
    }
    __syncthreads();

    if (t < PT && out_size >= RES_ELEMS + NPTS)
        out[RES_ELEMS + n0 + t] = (float)sidx[t];

    // gather winning code vectors (emb L2-hot), coalesced stores
    float* ob = out + bb * (D_ * HW_) + rem0;
#pragma unroll 8
    for (int i = 0; i < 32; ++i) {
        int flat = t + NT * i;
        int p = flat & 127, d = flat >> 7;
        ob[d * HW_ + p] = __ldg(&emb[d * K_ + sidx[p]]);
    }
}

extern "C" void kernel_launch(void* const* d_in, const int* in_sizes, int n_in,
                              void* d_out, int out_size)
{
    const float* x   = (const float*)d_in[0];
    const float* emb = (const float*)d_in[1];
    if (n_in >= 2 && in_sizes[0] == D_ * K_ && in_sizes[1] == RES_ELEMS) {
        x   = (const float*)d_in[1];
        emb = (const float*)d_in[0];
    }
    static int configured = 0;
    if (!configured) {
        cudaFuncSetAttribute(vq_mma_kernel, cudaFuncAttributeMaxDynamicSharedMemorySize, SMEM_TOTAL);
        configured = 1;
    }
    prep_split<<<64, 256>>>(emb);
    prep_ssq<<<4, 256>>>(emb);
    vq_mma_kernel<<<NPTS / PT, NT, SMEM_TOTAL>>>(x, emb, (float*)d_out, out_size);
}